// round 8
// baseline (speedup 1.0000x reference)
#include <cuda_runtime.h>
#include <cuda_fp16.h>
#include <cstdint>

#define NTOK 16384
#define DIN  1024
#define DOUT 1024
#define NEXP 8

// ---------------- device-global scratch (no runtime allocation allowed) ----
__device__ __align__(128) __half g_A[NTOK * DIN];
__device__ __align__(128) __half g_W[NEXP * DOUT * DIN];
__device__ __align__(128) float g_c[NEXP * DOUT];       // c[e,o] = bias[e] . W[e,o]
__device__ __align__(128) float g_probs[NTOK * NEXP];   // softmax gate probs
__device__ __align__(128) float g_expert_scratch[(size_t)NTOK * NEXP * DOUT];

// ---------------- helpers -----------------------------------------------------
static __device__ __forceinline__ void cp16(uint32_t smaddr, const void* gptr) {
    asm volatile("cp.async.cg.shared.global [%0], [%1], 16;" :: "r"(smaddr), "l"(gptr));
}
#define CP_COMMIT() asm volatile("cp.async.commit_group;" ::: "memory")
#define CP_WAIT(n)  asm volatile("cp.async.wait_group %0;" :: "n"(n) : "memory")

static __device__ __forceinline__ uint32_t smem_u32(const void* p) {
    uint32_t a;
    asm("{ .reg .u64 t; cvta.to.shared.u64 t, %1; cvt.u32.u64 %0, t; }" : "=r"(a) : "l"(p));
    return a;
}

static __device__ __forceinline__ void ldsm_x4(uint32_t* r, uint32_t addr) {
    asm volatile("ldmatrix.sync.aligned.m8n8.x4.shared.b16 {%0,%1,%2,%3}, [%4];"
                 : "=r"(r[0]), "=r"(r[1]), "=r"(r[2]), "=r"(r[3]) : "r"(addr));
}

static __device__ __forceinline__ void mma_fp16(float* d, const uint32_t* a,
                                                uint32_t b0, uint32_t b1) {
    asm volatile(
        "mma.sync.aligned.m16n8k16.row.col.f32.f16.f16.f32 "
        "{%0,%1,%2,%3}, {%4,%5,%6,%7}, {%8,%9}, {%0,%1,%2,%3};"
        : "+f"(d[0]), "+f"(d[1]), "+f"(d[2]), "+f"(d[3])
        : "r"(a[0]), "r"(a[1]), "r"(a[2]), "r"(a[3]), "r"(b0), "r"(b1));
}

// ---------------- GEMM tiling --------------------------------------------------
static constexpr int M_TILE  = 64;         // tokens per CTA
static constexpr int N_TILE  = 256;        // 8 experts * 32 o-cols
static constexpr int NO_TILE = 32;
static constexpr int KC      = 32;         // K elems per chunk
static constexpr int CHUNKS  = DIN / KC;   // 32
static constexpr int NPAIR   = CHUNKS / 2; // 16 (one barrier per pair)
static constexpr int ROWB    = 80;         // smem row stride bytes (64 + 16 pad)
static constexpr int A_BYTES = M_TILE * ROWB;         // 5120
static constexpr int B_BYTES = N_TILE * ROWB;         // 20480
static constexpr int STAGE   = A_BYTES + B_BYTES;     // 25600
static constexpr int SMEM_DYN = 4 * STAGE;            // 102400
static constexpr int MS_STRIDE = 34;       // msum row stride (floats)

// ---------------- prep 1: embs -> fp16 + gating softmax (one warp per token) ---
__global__ void __launch_bounds__(256) prep_A_gate_kernel(const float* __restrict__ embs,
                                                          const float* __restrict__ expsT) {
    const int tok = blockIdx.x * 8 + (threadIdx.x >> 5);
    const int lid = threadIdx.x & 31;
    const float4* row = reinterpret_cast<const float4*>(embs + (size_t)tok * DIN);
    __half2* arow = reinterpret_cast<__half2*>(g_A + (size_t)tok * DIN);
    float acc[NEXP];
#pragma unroll
    for (int e = 0; e < NEXP; ++e) acc[e] = 0.f;

#pragma unroll
    for (int j = 0; j < 8; ++j) {
        const int k4 = lid + j * 32;            // float4 index; k = 4*k4
        const float4 v = row[k4];
        arow[2 * k4]     = __floats2half2_rn(v.x, v.y);
        arow[2 * k4 + 1] = __floats2half2_rn(v.z, v.w);
        const float* t = expsT + (size_t)k4 * 4 * NEXP;
#pragma unroll
        for (int r = 0; r < 4; ++r) {
            const float xv = (&v.x)[r];
            const float4 g0 = reinterpret_cast<const float4*>(t + r * NEXP)[0];
            const float4 g1 = reinterpret_cast<const float4*>(t + r * NEXP)[1];
            acc[0] += xv * g0.x; acc[1] += xv * g0.y;
            acc[2] += xv * g0.z; acc[3] += xv * g0.w;
            acc[4] += xv * g1.x; acc[5] += xv * g1.y;
            acc[6] += xv * g1.z; acc[7] += xv * g1.w;
        }
    }
#pragma unroll
    for (int e = 0; e < NEXP; ++e)
#pragma unroll
        for (int off = 16; off; off >>= 1)
            acc[e] += __shfl_xor_sync(0xFFFFFFFFu, acc[e], off);
    if (lid == 0) {
        float mx = acc[0];
#pragma unroll
        for (int e = 1; e < NEXP; ++e) mx = fmaxf(mx, acc[e]);
        float ex[NEXP], s = 0.f;
#pragma unroll
        for (int e = 0; e < NEXP; ++e) { ex[e] = expf(acc[e] - mx); s += ex[e]; }
        const float inv = 1.f / s;
#pragma unroll
        for (int e = 0; e < NEXP; ++e) g_probs[(size_t)tok * NEXP + e] = ex[e] * inv;
    }
}

// ---------------- prep 2: W -> fp16 + c[e,o] (one warp per (e,o) row) ----------
__global__ void __launch_bounds__(256) prep_W_bias_kernel(const float* __restrict__ W,
                                                          const float* __restrict__ bias) {
    const int w = blockIdx.x * 8 + (threadIdx.x >> 5);
    const int lid = threadIdx.x & 31;
    const int e = w >> 10;
    const float4* wr = reinterpret_cast<const float4*>(W + (size_t)w * DIN);
    const float4* br = reinterpret_cast<const float4*>(bias + (size_t)e * DIN);
    __half2* wrow = reinterpret_cast<__half2*>(g_W + (size_t)w * DIN);
    float acc = 0.f;
#pragma unroll
    for (int j = 0; j < 8; ++j) {
        const int k4 = lid + j * 32;
        const float4 v = wr[k4];
        const float4 b = br[k4];
        wrow[2 * k4]     = __floats2half2_rn(v.x, v.y);
        wrow[2 * k4 + 1] = __floats2half2_rn(v.z, v.w);
        acc += v.x * b.x + v.y * b.y + v.z * b.z + v.w * b.w;
    }
#pragma unroll
    for (int off = 16; off; off >>= 1) acc += __shfl_xor_sync(0xFFFFFFFFu, acc, off);
    if (lid == 0) g_c[w] = acc;
}

// ---------------- main GEMM: fp16, pair-chunked, 1 barrier per 2 chunks --------
__global__ void __launch_bounds__(256, 2)
moe_gemm_kernel(float* __restrict__ d_expert, float* __restrict__ d_multi) {
    extern __shared__ char sm[];
    const uint32_t sb = smem_u32(sm);
    const int tid = threadIdx.x;
    const int wid = tid >> 5;
    const int lid = tid & 31;
    const int g   = lid >> 2;     // 0..7
    const int tig = lid & 3;      // 0..3
    const int warp_m = wid & 1;   // 2 warp rows (32 m each)
    const int warp_n = wid >> 1;  // 4 warp cols (64 n each)
    const int o0 = blockIdx.x * NO_TILE;
    const int m0 = blockIdx.y * M_TILE;

    // --- cp.async source/destination ---
    const int cr = tid >> 2, cq = tid & 3;
    const __half* aptr = g_A + (size_t)(m0 + cr) * DIN + cq * 8;
    const __half* bptr = g_W + (size_t)((cr >> 5) * DOUT + o0 + (cr & 31)) * DIN + cq * 8;
    const uint32_t a_dst = (uint32_t)(cr * ROWB + cq * 16);
    const uint32_t b_dst = (uint32_t)(A_BYTES + cr * ROWB + cq * 16);
    static constexpr size_t BSEG = (size_t)2 * DOUT * DIN;

    // --- ldsm lane addresses ---
    const int q8 = lid >> 3, r8 = lid & 7;
    const uint32_t a_lane = (uint32_t)((warp_m * 32 + (q8 & 1) * 8 + r8) * ROWB + (q8 >> 1) * 16);
    const uint32_t b_lane = (uint32_t)(A_BYTES + (warp_n * 64 + (q8 >> 1) * 8 + r8) * ROWB + (q8 & 1) * 16);

    float acc[2][8][4];
#pragma unroll
    for (int mt = 0; mt < 2; ++mt)
#pragma unroll
        for (int nt = 0; nt < 8; ++nt)
#pragma unroll
            for (int r = 0; r < 4; ++r) acc[mt][nt][r] = 0.f;

    // --- prologue: issue pairs 0 (chunks 0,1) and 1 (chunks 2,3) ---
#pragma unroll
    for (int p = 0; p < 2; ++p) {
#pragma unroll
        for (int h = 0; h < 2; ++h) {
            const uint32_t base = sb + (2 * p + h) * STAGE;
            cp16(base + a_dst, aptr);
#pragma unroll
            for (int i = 0; i < 4; ++i)
                cp16(base + b_dst + i * (64 * ROWB), bptr + (size_t)i * BSEG);
            aptr += KC; bptr += KC;
        }
        CP_COMMIT();
    }
    CP_WAIT(1);
    __syncthreads();

    uint32_t A0f[2][4], A1f[2][4], B0f[4][4], B1f[4][4];
#pragma unroll
    for (int mt = 0; mt < 2; ++mt) ldsm_x4(A0f[mt], sb + a_lane + mt * 16 * ROWB);
#pragma unroll
    for (int p = 0; p < 4; ++p)   ldsm_x4(B0f[p], sb + b_lane + p * 16 * ROWB);

#define MMA_SET(Af, Bf)                                               \
    _Pragma("unroll")                                                 \
    for (int p_ = 0; p_ < 4; ++p_) {                                  \
        mma_fp16(acc[0][2 * p_ + 0], Af[0], Bf[p_][0], Bf[p_][1]);    \
        mma_fp16(acc[1][2 * p_ + 0], Af[1], Bf[p_][0], Bf[p_][1]);    \
        mma_fp16(acc[0][2 * p_ + 1], Af[0], Bf[p_][2], Bf[p_][3]);    \
        mma_fp16(acc[1][2 * p_ + 1], Af[1], Bf[p_][2], Bf[p_][3]);    \
    }

#pragma unroll 1
    for (int pr = 0; pr < NPAIR; ++pr) {
        const uint32_t s0 = sb + ((2 * pr) & 3) * STAGE;
        const uint32_t s1 = sb + ((2 * pr + 1) & 3) * STAGE;

        // k-step (c0, ks1)
#pragma unroll
        for (int p = 0; p < 4; ++p) ldsm_x4(B1f[p], s0 + b_lane + p * 16 * ROWB + 32);
        MMA_SET(A0f, B0f);
#pragma unroll
        for (int mt = 0; mt < 2; ++mt) ldsm_x4(A1f[mt], s0 + a_lane + mt * 16 * ROWB + 32);

        // k-step (c0+1, ks0)
#pragma unroll
        for (int p = 0; p < 4; ++p) ldsm_x4(B0f[p], s1 + b_lane + p * 16 * ROWB);
        MMA_SET(A1f, B1f);
#pragma unroll
        for (int mt = 0; mt < 2; ++mt) ldsm_x4(A0f[mt], s1 + a_lane + mt * 16 * ROWB);

        // k-step (c0+1, ks1)
#pragma unroll
        for (int p = 0; p < 4; ++p) ldsm_x4(B1f[p], s1 + b_lane + p * 16 * ROWB + 32);
        MMA_SET(A0f, B0f);
#pragma unroll
        for (int mt = 0; mt < 2; ++mt) ldsm_x4(A1f[mt], s1 + a_lane + mt * 16 * ROWB + 32);

        // final k-step MMAs of the pair
        MMA_SET(A1f, B1f);

        if (pr + 1 < NPAIR) {
            CP_WAIT(0);          // pair pr+1 resident
            __syncthreads();     // all warps done reading pair pr stages
            if (pr + 2 < NPAIR) {  // refill pair pr's stages with pair pr+2
#pragma unroll
                for (int h = 0; h < 2; ++h) {
                    const uint32_t base = sb + ((2 * pr + h) & 3) * STAGE;
                    cp16(base + a_dst, aptr);
#pragma unroll
                    for (int i = 0; i < 4; ++i)
                        cp16(base + b_dst + i * (64 * ROWB), bptr + (size_t)i * BSEG);
                    aptr += KC; bptr += KC;
                }
                CP_COMMIT();
            }
            const uint32_t sn = sb + ((2 * pr + 2) & 3) * STAGE;
#pragma unroll
            for (int p = 0; p < 4; ++p) ldsm_x4(B0f[p], sn + b_lane + p * 16 * ROWB);
#pragma unroll
            for (int mt = 0; mt < 2; ++mt) ldsm_x4(A0f[mt], sn + a_lane + mt * 16 * ROWB);
        }
    }
#undef MMA_SET

    // ---- epilogue 1: subtract c[e,o], write expert_outputs, keep ov in acc ----
#pragma unroll
    for (int mt = 0; mt < 2; ++mt) {
#pragma unroll
        for (int h = 0; h < 2; ++h) {
            const int m = m0 + warp_m * 32 + mt * 16 + h * 8 + g;
            float* erow = d_expert + (size_t)m * (NEXP * DOUT);
#pragma unroll
            for (int nt = 0; nt < 8; ++nt) {
                const int e = warp_n * 2 + (nt >> 2);
                const int o = o0 + (nt & 3) * 8 + tig * 2;
                const float2 cv = *reinterpret_cast<const float2*>(g_c + e * DOUT + o);
                float2 ov;
                ov.x = acc[mt][nt][h * 2 + 0] - cv.x;
                ov.y = acc[mt][nt][h * 2 + 1] - cv.y;
                *reinterpret_cast<float2*>(erow + e * DOUT + o) = ov;
                acc[mt][nt][h * 2 + 0] = ov.x;
                acc[mt][nt][h * 2 + 1] = ov.y;
            }
        }
    }

    // ---- epilogue 2: fused multi_out = sum_e p * ov via smem partial sums ----
    __syncthreads();
    float* msum = reinterpret_cast<float*>(sm);   // 64 x MS_STRIDE floats
    for (int i = tid; i < M_TILE * MS_STRIDE; i += 256) msum[i] = 0.f;
    __syncthreads();

#pragma unroll 1
    for (int rnd = 0; rnd < 4; ++rnd) {
        if (warp_n == rnd) {
#pragma unroll
            for (int mt = 0; mt < 2; ++mt)
#pragma unroll
                for (int h = 0; h < 2; ++h) {
                    const int ml = warp_m * 32 + mt * 16 + h * 8 + g;
                    const int m = m0 + ml;
                    const float p0 = g_probs[(size_t)m * NEXP + warp_n * 2 + 0];
                    const float p1 = g_probs[(size_t)m * NEXP + warp_n * 2 + 1];
#pragma unroll
                    for (int nt = 0; nt < 4; ++nt) {
                        const int j = nt * 8 + tig * 2;
                        const int idx = ml * MS_STRIDE + j;
                        msum[idx + 0] += p0 * acc[mt][nt][h * 2 + 0]
                                       + p1 * acc[mt][nt + 4][h * 2 + 0];
                        msum[idx + 1] += p0 * acc[mt][nt][h * 2 + 1]
                                       + p1 * acc[mt][nt + 4][h * 2 + 1];
                    }
                }
        }
        __syncthreads();
    }

    {   // write multi: 256 threads x 8 floats = 64 x 32
        const int row = tid >> 2;
        const int j0 = (tid & 3) * 8;
        float v[8];
#pragma unroll
        for (int t = 0; t < 8; ++t) v[t] = msum[row * MS_STRIDE + j0 + t];
        float4* mp = reinterpret_cast<float4*>(d_multi + (size_t)(m0 + row) * DOUT + o0 + j0);
        mp[0] = make_float4(v[0], v[1], v[2], v[3]);
        mp[1] = make_float4(v[4], v[5], v[6], v[7]);
    }
}

// ---------------- launch --------------------------------------------------------
extern "C" void kernel_launch(void* const* d_in, const int* in_sizes, int n_in,
                              void* d_out, int out_size) {
    (void)in_sizes; (void)n_in;
    const float* embs  = (const float*)d_in[0];
    const float* expsT = (const float*)d_in[1];
    const float* bias  = (const float*)d_in[2];
    const float* W     = (const float*)d_in[3];
    float* out = (float*)d_out;

    const long long multi_elems  = (long long)NTOK * DOUT;
    const long long expert_elems = (long long)NTOK * NEXP * DOUT;
    float* d_multi = out;
    float* d_expert;
    if ((long long)out_size >= multi_elems + expert_elems) {
        d_expert = out + multi_elems;
    } else {
        cudaGetSymbolAddress((void**)&d_expert, g_expert_scratch);
    }

    prep_A_gate_kernel<<<NTOK / 8, 256>>>(embs, expsT);
    prep_W_bias_kernel<<<NEXP * DOUT / 8, 256>>>(W, bias);

    cudaFuncSetAttribute(moe_gemm_kernel, cudaFuncAttributeMaxDynamicSharedMemorySize, SMEM_DYN);
    moe_gemm_kernel<<<dim3(DOUT / NO_TILE, NTOK / M_TILE), 256, SMEM_DYN>>>(d_expert, d_multi);
}

// round 9
// speedup vs baseline: 1.0792x; 1.0792x over previous
#include <cuda_runtime.h>
#include <cuda_fp16.h>
#include <cstdint>

#define NTOK 16384
#define DIN  1024
#define DOUT 1024
#define NEXP 8

// ---------------- device-global scratch (no runtime allocation allowed) ----
__device__ __align__(128) __half g_A[NTOK * DIN];
__device__ __align__(128) __half g_W[NEXP * DOUT * DIN];
__device__ __align__(128) float g_c[NEXP * DOUT];       // c[e,o] = bias[e] . W[e,o]
__device__ __align__(128) float g_probs[NTOK * NEXP];   // softmax gate probs
__device__ __align__(128) float g_expert_scratch[(size_t)NTOK * NEXP * DOUT];

// ---------------- helpers -----------------------------------------------------
static __device__ __forceinline__ void cp16(uint32_t smaddr, const void* gptr) {
    asm volatile("cp.async.cg.shared.global [%0], [%1], 16;" :: "r"(smaddr), "l"(gptr));
}
#define CP_COMMIT() asm volatile("cp.async.commit_group;" ::: "memory")
#define CP_WAIT(n)  asm volatile("cp.async.wait_group %0;" :: "n"(n) : "memory")

static __device__ __forceinline__ uint32_t smem_u32(const void* p) {
    uint32_t a;
    asm("{ .reg .u64 t; cvta.to.shared.u64 t, %1; cvt.u32.u64 %0, t; }" : "=r"(a) : "l"(p));
    return a;
}

static __device__ __forceinline__ void ldsm_x4(uint32_t* r, uint32_t addr) {
    asm volatile("ldmatrix.sync.aligned.m8n8.x4.shared.b16 {%0,%1,%2,%3}, [%4];"
                 : "=r"(r[0]), "=r"(r[1]), "=r"(r[2]), "=r"(r[3]) : "r"(addr));
}

static __device__ __forceinline__ void mma_fp16(float* d, const uint32_t* a,
                                                uint32_t b0, uint32_t b1) {
    asm volatile(
        "mma.sync.aligned.m16n8k16.row.col.f32.f16.f16.f32 "
        "{%0,%1,%2,%3}, {%4,%5,%6,%7}, {%8,%9}, {%0,%1,%2,%3};"
        : "+f"(d[0]), "+f"(d[1]), "+f"(d[2]), "+f"(d[3])
        : "r"(a[0]), "r"(a[1]), "r"(a[2]), "r"(a[3]), "r"(b0), "r"(b1));
}

// ---------------- GEMM tiling --------------------------------------------------
static constexpr int M_TILE  = 64;         // tokens per CTA
static constexpr int N_TILE  = 256;        // 8 experts * 32 o-cols
static constexpr int NO_TILE = 32;
static constexpr int KC      = 32;         // K elems per chunk
static constexpr int CHUNKS  = DIN / KC;   // 32
static constexpr int ROWB    = 80;         // smem row stride bytes (64 + 16 pad)
static constexpr int A_BYTES = M_TILE * ROWB;         // 5120
static constexpr int B_BYTES = N_TILE * ROWB;         // 20480
static constexpr int STAGE   = A_BYTES + B_BYTES;     // 25600
static constexpr int NSTAGE  = 4;
static constexpr int SMEM_DYN = NSTAGE * STAGE;       // 102400
static constexpr int MS_STRIDE = 34;       // msum row stride (floats)

// ---------------- prep 1: embs -> fp16 ----------------------------------------
__global__ void convert_A_kernel(const float* __restrict__ embs) {
    int i = blockIdx.x * 256 + threadIdx.x;
    float4 v = reinterpret_cast<const float4*>(embs)[i];
    __half2* hp = reinterpret_cast<__half2*>(g_A);
    hp[2 * i]     = __floats2half2_rn(v.x, v.y);
    hp[2 * i + 1] = __floats2half2_rn(v.z, v.w);
}

// ---------------- prep 2: W -> fp16 + c[e,o] (one warp per (e,o) row) ----------
__global__ void __launch_bounds__(256) prep_W_bias_kernel(const float* __restrict__ W,
                                                          const float* __restrict__ bias) {
    const int w = blockIdx.x * 8 + (threadIdx.x >> 5);
    const int lid = threadIdx.x & 31;
    const int e = w >> 10;
    const float4* wr = reinterpret_cast<const float4*>(W + (size_t)w * DIN);
    const float4* br = reinterpret_cast<const float4*>(bias + (size_t)e * DIN);
    __half2* wrow = reinterpret_cast<__half2*>(g_W + (size_t)w * DIN);
    float acc = 0.f;
#pragma unroll
    for (int j = 0; j < 8; ++j) {
        const int k4 = lid + j * 32;
        const float4 v = wr[k4];
        const float4 b = br[k4];
        wrow[2 * k4]     = __floats2half2_rn(v.x, v.y);
        wrow[2 * k4 + 1] = __floats2half2_rn(v.z, v.w);
        acc += v.x * b.x + v.y * b.y + v.z * b.z + v.w * b.w;
    }
#pragma unroll
    for (int off = 16; off; off >>= 1) acc += __shfl_xor_sync(0xFFFFFFFFu, acc, off);
    if (lid == 0) g_c[w] = acc;
}

// ---------------- prep 3: gating softmax, expsT cached transposed in smem ------
__global__ void __launch_bounds__(256) gate_kernel(const float* __restrict__ embs,
                                                   const float* __restrict__ expsT) {
    __shared__ float sw[NEXP * DIN];    // sw[e*DIN + k], 32 KB
    const int tid = threadIdx.x;
    for (int i = tid; i < NEXP * DIN; i += 256) {
        const int k = i >> 3, e = i & 7;
        sw[e * DIN + k] = expsT[i];
    }
    __syncthreads();

    const int wid = tid >> 5;
    const int lid = tid & 31;
    const int n0 = (blockIdx.x * 8 + wid) * 4;
    float acc[4][NEXP];
#pragma unroll
    for (int t = 0; t < 4; ++t)
#pragma unroll
        for (int e = 0; e < NEXP; ++e) acc[t][e] = 0.f;

#pragma unroll 4
    for (int kc = 0; kc < DIN / 32; ++kc) {
        const int k = kc * 32 + lid;
        float w[NEXP];
#pragma unroll
        for (int e = 0; e < NEXP; ++e) w[e] = sw[e * DIN + k];
#pragma unroll
        for (int t = 0; t < 4; ++t) {
            const float x = embs[(size_t)(n0 + t) * DIN + k];
#pragma unroll
            for (int e = 0; e < NEXP; ++e) acc[t][e] += x * w[e];
        }
    }
#pragma unroll
    for (int t = 0; t < 4; ++t)
#pragma unroll
        for (int e = 0; e < NEXP; ++e)
#pragma unroll
            for (int off = 16; off; off >>= 1)
                acc[t][e] += __shfl_xor_sync(0xFFFFFFFFu, acc[t][e], off);
    if (lid == 0) {
#pragma unroll
        for (int t = 0; t < 4; ++t) {
            float mx = acc[t][0];
#pragma unroll
            for (int e = 1; e < NEXP; ++e) mx = fmaxf(mx, acc[t][e]);
            float ex[NEXP], s = 0.f;
#pragma unroll
            for (int e = 0; e < NEXP; ++e) { ex[e] = expf(acc[t][e] - mx); s += ex[e]; }
            const float inv = 1.f / s;
#pragma unroll
            for (int e = 0; e < NEXP; ++e) g_probs[(size_t)(n0 + t) * NEXP + e] = ex[e] * inv;
        }
    }
}

// ---------------- main GEMM: fp16, pipelined frags, 1 barrier/chunk (R7) -------
__global__ void __launch_bounds__(256, 2)
moe_gemm_kernel(float* __restrict__ d_expert, float* __restrict__ d_multi) {
    extern __shared__ char sm[];
    const uint32_t sb = smem_u32(sm);
    const int tid = threadIdx.x;
    const int wid = tid >> 5;
    const int lid = tid & 31;
    const int g   = lid >> 2;     // 0..7
    const int tig = lid & 3;      // 0..3
    const int warp_m = wid & 1;   // 2 warp rows (32 m each)
    const int warp_n = wid >> 1;  // 4 warp cols (64 n each)
    const int o0 = blockIdx.x * NO_TILE;
    const int m0 = blockIdx.y * M_TILE;

    const int cr = tid >> 2, cq = tid & 3;
    const __half* aptr = g_A + (size_t)(m0 + cr) * DIN + cq * 8;
    const __half* bptr = g_W + (size_t)((cr >> 5) * DOUT + o0 + (cr & 31)) * DIN + cq * 8;
    const uint32_t a_dst = (uint32_t)(cr * ROWB + cq * 16);
    const uint32_t b_dst = (uint32_t)(A_BYTES + cr * ROWB + cq * 16);
    static constexpr size_t BSEG = (size_t)2 * DOUT * DIN;

    const int q8 = lid >> 3, r8 = lid & 7;
    const uint32_t a_lane = (uint32_t)((warp_m * 32 + (q8 & 1) * 8 + r8) * ROWB + (q8 >> 1) * 16);
    const uint32_t b_lane = (uint32_t)(A_BYTES + (warp_n * 64 + (q8 >> 1) * 8 + r8) * ROWB + (q8 & 1) * 16);

    float acc[2][8][4];
#pragma unroll
    for (int mt = 0; mt < 2; ++mt)
#pragma unroll
        for (int nt = 0; nt < 8; ++nt)
#pragma unroll
            for (int r = 0; r < 4; ++r) acc[mt][nt][r] = 0.f;

#pragma unroll
    for (int c = 0; c < 4; ++c) {
        const uint32_t base = sb + c * STAGE;
        cp16(base + a_dst, aptr);
#pragma unroll
        for (int i = 0; i < 4; ++i)
            cp16(base + b_dst + i * (64 * ROWB), bptr + (size_t)i * BSEG);
        CP_COMMIT();
        aptr += KC; bptr += KC;
    }
    CP_WAIT(3);
    __syncthreads();

    uint32_t A0f[2][4], A1f[2][4], B0f[4][4], B1f[4][4];
#pragma unroll
    for (int mt = 0; mt < 2; ++mt) ldsm_x4(A0f[mt], sb + a_lane + mt * 16 * ROWB);
#pragma unroll
    for (int p = 0; p < 4; ++p)   ldsm_x4(B0f[p], sb + b_lane + p * 16 * ROWB);

#pragma unroll 1
    for (int c = 0; c < CHUNKS; ++c) {
        const uint32_t stq = sb + (c & 3) * STAGE;
#pragma unroll
        for (int p = 0; p < 4; ++p) ldsm_x4(B1f[p], stq + b_lane + p * 16 * ROWB + 32);
#pragma unroll
        for (int p = 0; p < 4; ++p) {
            mma_fp16(acc[0][2 * p + 0], A0f[0], B0f[p][0], B0f[p][1]);
            mma_fp16(acc[1][2 * p + 0], A0f[1], B0f[p][0], B0f[p][1]);
            mma_fp16(acc[0][2 * p + 1], A0f[0], B0f[p][2], B0f[p][3]);
            mma_fp16(acc[1][2 * p + 1], A0f[1], B0f[p][2], B0f[p][3]);
        }
#pragma unroll
        for (int mt = 0; mt < 2; ++mt) ldsm_x4(A1f[mt], stq + a_lane + mt * 16 * ROWB + 32);

        if (c + 1 < CHUNKS) {
            if (c <= CHUNKS - 4)      { CP_WAIT(2); }
            else if (c == CHUNKS - 3) { CP_WAIT(1); }
            else                      { CP_WAIT(0); }
            __syncthreads();
            if (c + 4 < CHUNKS) {
                const uint32_t base = sb + (c & 3) * STAGE;
                cp16(base + a_dst, aptr);
#pragma unroll
                for (int i = 0; i < 4; ++i)
                    cp16(base + b_dst + i * (64 * ROWB), bptr + (size_t)i * BSEG);
                CP_COMMIT();
                aptr += KC; bptr += KC;
            }
            const uint32_t stn = sb + ((c + 1) & 3) * STAGE;
#pragma unroll
            for (int p = 0; p < 4; ++p) ldsm_x4(B0f[p], stn + b_lane + p * 16 * ROWB);
#pragma unroll
            for (int p = 0; p < 4; ++p) {
                mma_fp16(acc[0][2 * p + 0], A1f[0], B1f[p][0], B1f[p][1]);
                mma_fp16(acc[1][2 * p + 0], A1f[1], B1f[p][0], B1f[p][1]);
                mma_fp16(acc[0][2 * p + 1], A1f[0], B1f[p][2], B1f[p][3]);
                mma_fp16(acc[1][2 * p + 1], A1f[1], B1f[p][2], B1f[p][3]);
            }
#pragma unroll
            for (int mt = 0; mt < 2; ++mt) ldsm_x4(A0f[mt], stn + a_lane + mt * 16 * ROWB);
        } else {
#pragma unroll
            for (int p = 0; p < 4; ++p) {
                mma_fp16(acc[0][2 * p + 0], A1f[0], B1f[p][0], B1f[p][1]);
                mma_fp16(acc[1][2 * p + 0], A1f[1], B1f[p][0], B1f[p][1]);
                mma_fp16(acc[0][2 * p + 1], A1f[0], B1f[p][2], B1f[p][3]);
                mma_fp16(acc[1][2 * p + 1], A1f[1], B1f[p][2], B1f[p][3]);
            }
        }
    }

    // ---- epilogue 1: subtract c[e,o], write expert_outputs, keep ov in acc ----
#pragma unroll
    for (int mt = 0; mt < 2; ++mt) {
#pragma unroll
        for (int h = 0; h < 2; ++h) {
            const int m = m0 + warp_m * 32 + mt * 16 + h * 8 + g;
            float* erow = d_expert + (size_t)m * (NEXP * DOUT);
#pragma unroll
            for (int nt = 0; nt < 8; ++nt) {
                const int e = warp_n * 2 + (nt >> 2);
                const int o = o0 + (nt & 3) * 8 + tig * 2;
                const float2 cv = *reinterpret_cast<const float2*>(g_c + e * DOUT + o);
                float2 ov;
                ov.x = acc[mt][nt][h * 2 + 0] - cv.x;
                ov.y = acc[mt][nt][h * 2 + 1] - cv.y;
                *reinterpret_cast<float2*>(erow + e * DOUT + o) = ov;
                acc[mt][nt][h * 2 + 0] = ov.x;
                acc[mt][nt][h * 2 + 1] = ov.y;
            }
        }
    }

    // ---- epilogue 2: fused multi_out = sum_e p * ov via smem partial sums ----
    __syncthreads();
    float* msum = reinterpret_cast<float*>(sm);   // 64 x MS_STRIDE floats
    for (int i = tid; i < M_TILE * MS_STRIDE; i += 256) msum[i] = 0.f;
    __syncthreads();

#pragma unroll 1
    for (int rnd = 0; rnd < 4; ++rnd) {
        if (warp_n == rnd) {
#pragma unroll
            for (int mt = 0; mt < 2; ++mt)
#pragma unroll
                for (int h = 0; h < 2; ++h) {
                    const int ml = warp_m * 32 + mt * 16 + h * 8 + g;
                    const int m = m0 + ml;
                    const float p0 = g_probs[(size_t)m * NEXP + warp_n * 2 + 0];
                    const float p1 = g_probs[(size_t)m * NEXP + warp_n * 2 + 1];
#pragma unroll
                    for (int nt = 0; nt < 4; ++nt) {
                        const int j = nt * 8 + tig * 2;
                        const int idx = ml * MS_STRIDE + j;
                        msum[idx + 0] += p0 * acc[mt][nt][h * 2 + 0]
                                       + p1 * acc[mt][nt + 4][h * 2 + 0];
                        msum[idx + 1] += p0 * acc[mt][nt][h * 2 + 1]
                                       + p1 * acc[mt][nt + 4][h * 2 + 1];
                    }
                }
        }
        __syncthreads();
    }

    {   // write multi: 256 threads x 8 floats = 64 x 32
        const int row = tid >> 2;
        const int j0 = (tid & 3) * 8;
        float v[8];
#pragma unroll
        for (int t = 0; t < 8; ++t) v[t] = msum[row * MS_STRIDE + j0 + t];
        float4* mp = reinterpret_cast<float4*>(d_multi + (size_t)(m0 + row) * DOUT + o0 + j0);
        mp[0] = make_float4(v[0], v[1], v[2], v[3]);
        mp[1] = make_float4(v[4], v[5], v[6], v[7]);
    }
}

// ---------------- launch --------------------------------------------------------
extern "C" void kernel_launch(void* const* d_in, const int* in_sizes, int n_in,
                              void* d_out, int out_size) {
    (void)in_sizes; (void)n_in;
    const float* embs  = (const float*)d_in[0];
    const float* expsT = (const float*)d_in[1];
    const float* bias  = (const float*)d_in[2];
    const float* W     = (const float*)d_in[3];
    float* out = (float*)d_out;

    const long long multi_elems  = (long long)NTOK * DOUT;
    const long long expert_elems = (long long)NTOK * NEXP * DOUT;
    float* d_multi = out;
    float* d_expert;
    if ((long long)out_size >= multi_elems + expert_elems) {
        d_expert = out + multi_elems;
    } else {
        cudaGetSymbolAddress((void**)&d_expert, g_expert_scratch);
    }

    convert_A_kernel<<<NTOK * DIN / 4 / 256, 256>>>(embs);
    prep_W_bias_kernel<<<NEXP * DOUT / 8, 256>>>(W, bias);
    gate_kernel<<<NTOK / 32, 256>>>(embs, expsT);

    cudaFuncSetAttribute(moe_gemm_kernel, cudaFuncAttributeMaxDynamicSharedMemorySize, SMEM_DYN);
    moe_gemm_kernel<<<dim3(DOUT / NO_TILE, NTOK / M_TILE), 256, SMEM_DYN>>>(d_expert, d_multi);
}